// round 1
// baseline (speedup 1.0000x reference)
#include <cuda_runtime.h>

// Problem constants (fixed by the dataset)
#define Nn 8192
#define Dd 256
#define NUM_T 256
#define CSPLIT 9          // column splits -> 9*64 = 576 blocks
#define BM 128
#define BN 128
#define BK 32
#define LDA 132           // padded smem row (floats)

// Scratch (allocation-free rule: __device__ globals)
__device__ float g_E[Nn * Dd];        // normalized, pre-scaled by sqrt(10)
__device__ int   g_cls[Nn];
__device__ float g_negP[CSPLIT * Nn];
__device__ float g_posP[CSPLIT * Nn];
__device__ int   g_is64;

// ---- packed f32x2 helpers (FFMA2 is PTX-only; ptxas won't auto-fuse) ----
__device__ __forceinline__ unsigned long long pack2(float lo, float hi) {
    unsigned long long r;
    asm("mov.b64 %0, {%1,%2};" : "=l"(r) : "f"(lo), "f"(hi));
    return r;
}
__device__ __forceinline__ void unpack2(unsigned long long v, float& lo, float& hi) {
    asm("mov.b64 {%0,%1}, %2;" : "=f"(lo), "=f"(hi) : "l"(v));
}
#define FMA2(d, a, b) asm("fma.rn.f32x2 %0, %1, %2, %0;" : "+l"(d) : "l"(a), "l"(b))

// ---- detect int64 vs int32 target dtype (JAX x64 flag ambiguity) ----
// If the buffer is int64 (values 0..63), every odd 32-bit word is 0.
// Reads only indices < 8192 ints: in-bounds under BOTH interpretations.
__global__ void detect_kernel(const int* __restrict__ t) {
    __shared__ int sor[8];
    int tid = threadIdx.x;
    int acc = 0;
    for (int k = tid; k < Nn / 2; k += NUM_T) acc |= t[2 * k + 1];
    acc = __reduce_or_sync(0xffffffffu, acc);
    if ((tid & 31) == 0) sor[tid >> 5] = acc;
    __syncthreads();
    if (tid == 0) {
        int v = 0;
#pragma unroll
        for (int i = 0; i < 8; i++) v |= sor[i];
        g_is64 = (v == 0) ? 1 : 0;
    }
}

// ---- normalize rows, fold in 1/sqrt(temperature)=sqrt(10); extract class ----
__global__ void norm_kernel(const float* __restrict__ emb, const void* __restrict__ tgt) {
    int row = blockIdx.x;
    int t = threadIdx.x;
    float v = emb[row * Dd + t];
    float sq = v * v;
#pragma unroll
    for (int o = 16; o > 0; o >>= 1) sq += __shfl_down_sync(0xffffffffu, sq, o);
    __shared__ float sm[8];
    if ((t & 31) == 0) sm[t >> 5] = sq;
    __syncthreads();
    float tot = 0.f;
#pragma unroll
    for (int i = 0; i < 8; i++) tot += sm[i];
    float scale = 3.16227766016838f / fmaxf(sqrtf(tot), 1e-8f);  // sqrt(10)/max(||e||,eps)
    g_E[row * Dd + t] = v * scale;
    if (t == 0) {
        g_cls[row] = g_is64 ? (int)((const long long*)tgt)[row]
                            : ((const int*)tgt)[row];
    }
}

// ---- fused GEMM (E @ E^T, pre-scaled) + exp + masked row sums ----
// 256 threads = 16x16, each computes an 8x8 micro-tile via packed FFMA2.
__global__ void __launch_bounds__(256, 1) main_kernel() {
    __shared__ float As[BK][LDA];   // A^T tile: As[k][row]
    __shared__ float Bs[BK][LDA];   // B^T tile: Bs[k][col]

    int tid = threadIdx.x;
    int tx = tid & 15, ty = tid >> 4;
    int rb = blockIdx.y * BM;
    int split = blockIdx.x;

    int clsR[8], clsC[8];
#pragma unroll
    for (int i = 0; i < 8; i++) clsR[i] = g_cls[rb + ty * 8 + i];

    float negAcc[8], posAcc[8];
#pragma unroll
    for (int i = 0; i < 8; i++) { negAcc[i] = 0.f; posAcc[i] = 0.f; }

    for (int ct = split; ct < Nn / BN; ct += CSPLIT) {
        int cb = ct * BN;
#pragma unroll
        for (int j = 0; j < 8; j++) clsC[j] = g_cls[cb + tx * 8 + j];

        unsigned long long acc[8][4];
#pragma unroll
        for (int i = 0; i < 8; i++)
#pragma unroll
            for (int j = 0; j < 4; j++) acc[i][j] = 0ull;

        for (int kp = 0; kp < Dd; kp += BK) {
            __syncthreads();  // previous readers done before overwrite
#pragma unroll
            for (int l = 0; l < 4; l++) {
                int idx = tid + l * NUM_T;      // 0..1023
                int r = idx >> 3;               // 0..127
                int kq = idx & 7;               // 0..7  (float4 within BK)
                float4 va = *(const float4*)&g_E[(rb + r) * Dd + kp + kq * 4];
                As[kq * 4 + 0][r] = va.x; As[kq * 4 + 1][r] = va.y;
                As[kq * 4 + 2][r] = va.z; As[kq * 4 + 3][r] = va.w;
                float4 vb = *(const float4*)&g_E[(cb + r) * Dd + kp + kq * 4];
                Bs[kq * 4 + 0][r] = vb.x; Bs[kq * 4 + 1][r] = vb.y;
                Bs[kq * 4 + 2][r] = vb.z; Bs[kq * 4 + 3][r] = vb.w;
            }
            __syncthreads();

#pragma unroll 8
            for (int k = 0; k < BK; k++) {
                float4 a0 = *(const float4*)&As[k][ty * 8];
                float4 a1 = *(const float4*)&As[k][ty * 8 + 4];
                float4 b0 = *(const float4*)&Bs[k][tx * 8];
                float4 b1 = *(const float4*)&Bs[k][tx * 8 + 4];
                unsigned long long pb0 = pack2(b0.x, b0.y);
                unsigned long long pb1 = pack2(b0.z, b0.w);
                unsigned long long pb2 = pack2(b1.x, b1.y);
                unsigned long long pb3 = pack2(b1.z, b1.w);
                float av[8] = {a0.x, a0.y, a0.z, a0.w, a1.x, a1.y, a1.z, a1.w};
#pragma unroll
                for (int i = 0; i < 8; i++) {
                    unsigned long long pa = pack2(av[i], av[i]);
                    FMA2(acc[i][0], pa, pb0);
                    FMA2(acc[i][1], pa, pb1);
                    FMA2(acc[i][2], pa, pb2);
                    FMA2(acc[i][3], pa, pb3);
                }
            }
        }

        // fused epilogue: exp + class-mask + row accumulation (sim already /T)
#pragma unroll
        for (int i = 0; i < 8; i++) {
            int r = rb + ty * 8 + i;
            int cr = clsR[i];
#pragma unroll
            for (int j = 0; j < 4; j++) {
                float s0, s1;
                unpack2(acc[i][j], s0, s1);
                int c0 = cb + tx * 8 + j * 2;
                float e0 = __expf(s0);
                float e1 = __expf(s1);
                if (clsC[j * 2] == cr) { if (c0 != r) posAcc[i] += e0; }
                else                   { negAcc[i] += e0; }
                if (clsC[j * 2 + 1] == cr) { if (c0 + 1 != r) posAcc[i] += e1; }
                else                       { negAcc[i] += e1; }
            }
        }
    }

    // cross-tx reduction (16 partials per row), deterministic, no atomics
    __syncthreads();
    float (*red)[16] = (float (*)[16]) & As[0][0];  // 8 KB reuse of As
#pragma unroll
    for (int i = 0; i < 8; i++) red[ty * 8 + i][tx] = negAcc[i];
    __syncthreads();
    if (tid < BM) {
        float s = 0.f;
#pragma unroll
        for (int x = 0; x < 16; x++) s += red[tid][x];
        g_negP[split * Nn + rb + tid] = s;
    }
    __syncthreads();
#pragma unroll
    for (int i = 0; i < 8; i++) red[ty * 8 + i][tx] = posAcc[i];
    __syncthreads();
    if (tid < BM) {
        float s = 0.f;
#pragma unroll
        for (int x = 0; x < 16; x++) s += red[tid][x];
        g_posP[split * Nn + rb + tid] = s;
    }
}

// ---- final: loss = sum_r log(neg_r) - log(pos_r), single block, deterministic ----
__global__ void finalize_kernel(float* __restrict__ out) {
    int t = threadIdx.x;
    float local = 0.f;
    for (int r = t; r < Nn; r += NUM_T) {
        float ng = 0.f, ps = 0.f;
#pragma unroll
        for (int s = 0; s < CSPLIT; s++) {
            ng += g_negP[s * Nn + r];
            ps += g_posP[s * Nn + r];
        }
        local += logf(ng) - logf(ps);
    }
#pragma unroll
    for (int o = 16; o > 0; o >>= 1) local += __shfl_down_sync(0xffffffffu, local, o);
    __shared__ float sm[8];
    if ((t & 31) == 0) sm[t >> 5] = local;
    __syncthreads();
    if (t == 0) {
        float tot = 0.f;
#pragma unroll
        for (int i = 0; i < 8; i++) tot += sm[i];
        out[0] = tot;
    }
}

extern "C" void kernel_launch(void* const* d_in, const int* in_sizes, int n_in,
                              void* d_out, int out_size) {
    const float* emb = (const float*)d_in[0];
    const void* tgt = d_in[1];

    detect_kernel<<<1, NUM_T>>>((const int*)tgt);
    norm_kernel<<<Nn, NUM_T>>>(emb, tgt);
    dim3 grid(CSPLIT, Nn / BM);
    main_kernel<<<grid, NUM_T>>>();
    finalize_kernel<<<1, NUM_T>>>((float*)d_out);
}

// round 3
// speedup vs baseline: 3.5314x; 3.5314x over previous
#include <cuda_runtime.h>
#include <cuda_bf16.h>
#include <cstdint>

// Problem constants
#define Nn 8192
#define Dd 256
#define K2 512            // concat [hi | lo] along K
#define SPLIT 2           // 64 rowblocks * 2 col-splits = 128 CTAs (1 wave)
#define BM 128
#define BN 128
#define BK 64
#define NGI 256           // 32 col tiles * 8 k-chunks

// SMEM layout (bytes)
#define SM_A 0                         // 128 x 512 bf16 = 131072
#define SM_B 131072                    // 2 stages x (128 x 64 bf16 = 16384)
#define SM_CLS 163840                  // 8192 ints = 32768
#define SM_TOTAL 196608

// Scratch (__device__ globals: allocation-free rule)
__device__ __nv_bfloat16 g_E2[Nn * K2];
__device__ int   g_cls[Nn];
__device__ float g_negP[SPLIT * Nn];
__device__ float g_posP[SPLIT * Nn];
__device__ int   g_is64;

// ---------------- PTX helpers (family-safe: no tcgen05) ----------------
__device__ __forceinline__ uint32_t smem_u32(const void* p) {
    uint32_t a;
    asm("{ .reg .u64 t; cvta.to.shared.u64 t, %1; cvt.u32.u64 %0, t; }" : "=r"(a) : "l"(p));
    return a;
}
#define CP16(dst, src) asm volatile("cp.async.cg.shared.global [%0], [%1], 16;" :: "r"(dst), "l"(src))
#define CP_COMMIT() asm volatile("cp.async.commit_group;" ::: "memory")
#define CP_WAIT0() asm volatile("cp.async.wait_group 0;" ::: "memory")
#define CP_WAIT1() asm volatile("cp.async.wait_group 1;" ::: "memory")

#define LDM4(r, a) \
    asm volatile("ldmatrix.sync.aligned.m8n8.x4.shared.b16 {%0,%1,%2,%3}, [%4];" \
        : "=r"((r)[0]), "=r"((r)[1]), "=r"((r)[2]), "=r"((r)[3]) : "r"(a))

#define MMA(c, a, b0, b1) \
    asm volatile("mma.sync.aligned.m16n8k16.row.col.f32.bf16.bf16.f32 " \
        "{%0,%1,%2,%3}, {%4,%5,%6,%7}, {%8,%9}, {%0,%1,%2,%3};" \
        : "+f"((c)[0]), "+f"((c)[1]), "+f"((c)[2]), "+f"((c)[3]) \
        : "r"((a)[0]), "r"((a)[1]), "r"((a)[2]), "r"((a)[3]), "r"(b0), "r"(b1))

// ---------------- setup kernels ----------------
__global__ void detect_kernel(const int* __restrict__ t) {
    __shared__ int sor[8];
    int tid = threadIdx.x;
    int acc = 0;
    for (int k = tid; k < Nn / 2; k += 256) acc |= t[2 * k + 1];
    acc = __reduce_or_sync(0xffffffffu, acc);
    if ((tid & 31) == 0) sor[tid >> 5] = acc;
    __syncthreads();
    if (tid == 0) {
        int v = 0;
#pragma unroll
        for (int i = 0; i < 8; i++) v |= sor[i];
        g_is64 = (v == 0) ? 1 : 0;
    }
}

__global__ void norm_kernel(const float* __restrict__ emb, const void* __restrict__ tgt) {
    int row = blockIdx.x;
    int t = threadIdx.x;
    float v = emb[row * Dd + t];
    float sq = v * v;
#pragma unroll
    for (int o = 16; o > 0; o >>= 1) sq += __shfl_down_sync(0xffffffffu, sq, o);
    __shared__ float sm[8];
    if ((t & 31) == 0) sm[t >> 5] = sq;
    __syncthreads();
    float tot = 0.f;
#pragma unroll
    for (int i = 0; i < 8; i++) tot += sm[i];
    float scale = 3.16227766016838f / fmaxf(sqrtf(tot), 1e-8f);  // sqrt(10)/max(||e||,eps)
    float e = v * scale;
    __nv_bfloat16 h = __float2bfloat16(e);
    float lo = e - __bfloat162float(h);
    g_E2[row * K2 + t] = h;                      // hi half: cols [0,256)
    g_E2[row * K2 + Dd + t] = __float2bfloat16(lo);  // lo half: cols [256,512)
    if (t == 0) {
        g_cls[row] = g_is64 ? (int)((const long long*)tgt)[row]
                            : ((const int*)tgt)[row];
    }
}

// ---------------- main fused HMMA kernel ----------------
__device__ __forceinline__ void loadB(uint32_t sb, int stage, int ct, int kb, int tid) {
    uint32_t base = sb + SM_B + stage * 16384;
#pragma unroll
    for (int it = 0; it < 4; it++) {
        int idx = it * 256 + tid;
        int r = idx >> 3, c = idx & 7;
        uint32_t dst = base + r * 128 + ((c ^ (r & 7)) << 4);
        const char* src = (const char*)&g_E2[(ct * BN + r) * K2] + kb * 128 + c * 16;
        CP16(dst, src);
    }
}

__global__ void __launch_bounds__(256, 1) main_kernel() {
    extern __shared__ char smem[];
    uint32_t sb = smem_u32(smem);
    int tid = threadIdx.x, lane = tid & 31, wid = tid >> 5;
    int wr = wid & 3, wc = wid >> 2;       // 4 row-warps x 2 col-warps
    int split = blockIdx.x, rb = blockIdx.y * BM;
    int laneHi = lane >> 4;

    // class table -> smem (plain stores)
    int4* clsS4 = (int4*)(smem + SM_CLS);
    for (int i = tid; i < Nn / 4; i += 256) clsS4[i] = ((const int4*)g_cls)[i];
    const int* clsS = (const int*)(smem + SM_CLS);

    // A resident: 128 x 512 bf16, swizzled (chunk ^= row&7) for ldmatrix
#pragma unroll
    for (int it = 0; it < 32; it++) {
        int idx = it * 256 + tid;
        int r = idx >> 6, c = idx & 63;
        uint32_t dst = sb + SM_A + r * 1024 + ((c ^ (r & 7)) << 4);
        const char* src = (const char*)&g_E2[(rb + r) * K2] + c * 16;
        CP16(dst, src);
    }
    loadB(sb, 0, split * 32, 0, tid);
    CP_COMMIT();                            // group G0 = {A, B(0)}

    __syncthreads();                        // cls table visible

    // per-thread row ownership (C fragment rows)
    int rowG[4], clsR[4];
#pragma unroll
    for (int s = 0; s < 4; s++) {
        rowG[s] = rb + wr * 32 + (s >> 1) * 16 + (s & 1) * 8 + (lane >> 2);
        clsR[s] = clsS[rowG[s]];
    }
    float negA[4] = {0.f, 0.f, 0.f, 0.f}, posA[4] = {0.f, 0.f, 0.f, 0.f};

    // fragment address bases
    uint32_t aAddr[2]; int axor[2];
#pragma unroll
    for (int i = 0; i < 2; i++) {
        int r = wr * 32 + i * 16 + (lane & 15);
        aAddr[i] = sb + SM_A + r * 1024;
        axor[i] = r & 7;
    }
    uint32_t bAddr[4]; int bxor[4];
#pragma unroll
    for (int g = 0; g < 4; g++) {
        int r = wc * 64 + g * 16 + (lane & 15);
        bAddr[g] = r * 128;
        bxor[g] = r & 7;
    }

    float cAcc[2][8][4];
#pragma unroll
    for (int i = 0; i < 2; i++)
#pragma unroll
        for (int n = 0; n < 8; n++)
#pragma unroll
            for (int v = 0; v < 4; v++) cAcc[i][n][v] = 0.f;

    for (int gi = 0; gi < NGI; gi++) {
        int st = gi & 1;
        if (gi + 1 < NGI) {
            int gn = gi + 1;
            loadB(sb, st ^ 1, split * 32 + (gn >> 3), gn & 7, tid);
            CP_COMMIT();
            CP_WAIT1();
        } else {
            CP_WAIT0();
        }
        __syncthreads();                     // B(gi) visible (and A at gi=0)

        int kb = gi & 7;
        uint32_t bBase = sb + SM_B + st * 16384;
#pragma unroll
        for (int ks = 0; ks < 4; ks++) {
            uint32_t a[2][4], b[4][4];
            int chA = kb * 8 + ks * 2 + laneHi;
            int chB = ks * 2 + laneHi;
#pragma unroll
            for (int i = 0; i < 2; i++) LDM4(a[i], aAddr[i] + ((chA ^ axor[i]) << 4));
#pragma unroll
            for (int g = 0; g < 4; g++) LDM4(b[g], bBase + bAddr[g] + ((chB ^ bxor[g]) << 4));
#pragma unroll
            for (int i = 0; i < 2; i++)
#pragma unroll
                for (int n = 0; n < 8; n++)
                    MMA(cAcc[i][n], a[i], b[n >> 1][n & 1], b[n >> 1][(n & 1) + 2]);
        }

        if (kb == 7) {
            // fused epilogue for col tile ct: exp + mask + row accumulation
            int ct = split * 32 + (gi >> 3);
            int cb = ct * 128 + wc * 64 + (lane & 3) * 2;
#pragma unroll
            for (int n = 0; n < 8; n++) {
                int col0 = cb + n * 8, col1 = col0 + 1;
                int k0 = clsS[col0], k1 = clsS[col1];
#pragma unroll
                for (int i = 0; i < 2; i++) {
                    int s0 = i * 2, s1 = i * 2 + 1;
                    float e0 = __expf(cAcc[i][n][0]);
                    float e1 = __expf(cAcc[i][n][1]);
                    float e2 = __expf(cAcc[i][n][2]);
                    float e3 = __expf(cAcc[i][n][3]);
                    if (k0 == clsR[s0]) { if (col0 != rowG[s0]) posA[s0] += e0; } else negA[s0] += e0;
                    if (k1 == clsR[s0]) { if (col1 != rowG[s0]) posA[s0] += e1; } else negA[s0] += e1;
                    if (k0 == clsR[s1]) { if (col0 != rowG[s1]) posA[s1] += e2; } else negA[s1] += e2;
                    if (k1 == clsR[s1]) { if (col1 != rowG[s1]) posA[s1] += e3; } else negA[s1] += e3;
                    cAcc[i][n][0] = 0.f; cAcc[i][n][1] = 0.f;
                    cAcc[i][n][2] = 0.f; cAcc[i][n][3] = 0.f;
                }
            }
        }
        __syncthreads();                     // stage reuse guard
    }

    // reduce the 4 lanes sharing each row (butterfly), then cross-warpCol via smem
#pragma unroll
    for (int s = 0; s < 4; s++) {
        negA[s] += __shfl_xor_sync(0xffffffffu, negA[s], 1);
        negA[s] += __shfl_xor_sync(0xffffffffu, negA[s], 2);
        posA[s] += __shfl_xor_sync(0xffffffffu, posA[s], 1);
        posA[s] += __shfl_xor_sync(0xffffffffu, posA[s], 2);
    }
    float* sneg = (float*)(smem + SM_B);     // reuse B region: 2x128 floats
    float* spos = sneg + 256;
    if ((lane & 3) == 0) {
#pragma unroll
        for (int s = 0; s < 4; s++) {
            int rl = wr * 32 + (s >> 1) * 16 + (s & 1) * 8 + (lane >> 2);
            sneg[wc * 128 + rl] = negA[s];
            spos[wc * 128 + rl] = posA[s];
        }
    }
    __syncthreads();
    if (tid < 128) {
        g_negP[split * Nn + rb + tid] = sneg[tid] + sneg[128 + tid];
        g_posP[split * Nn + rb + tid] = spos[tid] + spos[128 + tid];
    }
}

// ---------------- finalize ----------------
__global__ void finalize_kernel(float* __restrict__ out) {
    int t = threadIdx.x;
    float local = 0.f;
    for (int r = t; r < Nn; r += 256) {
        float ng = 0.f, ps = 0.f;
#pragma unroll
        for (int s = 0; s < SPLIT; s++) {
            ng += g_negP[s * Nn + r];
            ps += g_posP[s * Nn + r];
        }
        local += logf(ng) - logf(ps);
    }
#pragma unroll
    for (int o = 16; o > 0; o >>= 1) local += __shfl_down_sync(0xffffffffu, local, o);
    __shared__ float sm[8];
    if ((t & 31) == 0) sm[t >> 5] = local;
    __syncthreads();
    if (t == 0) {
        float tot = 0.f;
#pragma unroll
        for (int i = 0; i < 8; i++) tot += sm[i];
        out[0] = tot;
    }
}

extern "C" void kernel_launch(void* const* d_in, const int* in_sizes, int n_in,
                              void* d_out, int out_size) {
    const float* emb = (const float*)d_in[0];
    const void* tgt = d_in[1];

    cudaFuncSetAttribute(main_kernel, cudaFuncAttributeMaxDynamicSharedMemorySize, SM_TOTAL);

    detect_kernel<<<1, 256>>>((const int*)tgt);
    norm_kernel<<<Nn, 256>>>(emb, tgt);
    dim3 grid(SPLIT, Nn / BM);
    main_kernel<<<grid, 256, SM_TOTAL>>>();
    finalize_kernel<<<1, 256>>>((float*)d_out);
}

// round 4
// speedup vs baseline: 6.4266x; 1.8199x over previous
#include <cuda_runtime.h>
#include <cuda_bf16.h>
#include <cstdint>

// Problem constants
#define Nn 8192
#define Dd 256
#define K2 512            // concat [hi | lo] along K
#define NBLK 64           // 8192 / 128
#define NTILES 2080       // upper triangle incl diagonal: 64*65/2
#define GRID_MAIN 152

// SMEM layout (bytes): 2-stage A (32KB) + 2-stage B (32KB) + reduction area
#define STAGE_SZ 32768
#define SM_AOFF(s) ((s) * STAGE_SZ)
#define SM_BOFF(s) (65536 + (s) * STAGE_SZ)
#define SM_RED 131072
#define SM_TOTAL (131072 + 6144)

// Scratch (__device__ globals: allocation-free rule)
__device__ __nv_bfloat16 g_E2[Nn * K2];
__device__ int   g_cls[Nn];
__device__ float g_negP[NBLK * Nn];   // slot s, row r: partial from tile (min(s,blk(r)),max(...))
__device__ float g_posP[NBLK * Nn];
__device__ float g_lossP[32];
__device__ int   g_is64;
__device__ unsigned char g_ti[NTILES], g_tj[NTILES];

// ---------------- PTX helpers (family-safe: no tcgen05) ----------------
__device__ __forceinline__ uint32_t smem_u32(const void* p) {
    uint32_t a;
    asm("{ .reg .u64 t; cvta.to.shared.u64 t, %1; cvt.u32.u64 %0, t; }" : "=r"(a) : "l"(p));
    return a;
}
#define CP16(dst, src) asm volatile("cp.async.cg.shared.global [%0], [%1], 16;" :: "r"(dst), "l"(src))
#define CP_COMMIT() asm volatile("cp.async.commit_group;" ::: "memory")
#define CP_WAIT0() asm volatile("cp.async.wait_group 0;" ::: "memory")
#define CP_WAIT1() asm volatile("cp.async.wait_group 1;" ::: "memory")

#define LDM4(r, a) \
    asm volatile("ldmatrix.sync.aligned.m8n8.x4.shared.b16 {%0,%1,%2,%3}, [%4];" \
        : "=r"((r)[0]), "=r"((r)[1]), "=r"((r)[2]), "=r"((r)[3]) : "r"(a))

#define MMA(c, a, b0, b1) \
    asm volatile("mma.sync.aligned.m16n8k16.row.col.f32.bf16.bf16.f32 " \
        "{%0,%1,%2,%3}, {%4,%5,%6,%7}, {%8,%9}, {%0,%1,%2,%3};" \
        : "+f"((c)[0]), "+f"((c)[1]), "+f"((c)[2]), "+f"((c)[3]) \
        : "r"((a)[0]), "r"((a)[1]), "r"((a)[2]), "r"((a)[3]), "r"(b0), "r"(b1))

// ---------------- setup kernels ----------------
__global__ void detect_kernel(const int* __restrict__ t) {
    __shared__ int sor[8];
    int tid = threadIdx.x;
    int acc = 0;
    for (int k = tid; k < Nn / 2; k += 256) acc |= t[2 * k + 1];
    acc = __reduce_or_sync(0xffffffffu, acc);
    if ((tid & 31) == 0) sor[tid >> 5] = acc;
    __syncthreads();
    if (tid == 0) {
        int v = 0;
#pragma unroll
        for (int i = 0; i < 8; i++) v |= sor[i];
        g_is64 = (v == 0) ? 1 : 0;
    }
    // triangle tile map
    for (int tt = tid; tt < NTILES; tt += 256) {
        int i = 0, rem = tt;
        while (rem >= NBLK - i) { rem -= NBLK - i; i++; }
        g_ti[tt] = (unsigned char)i;
        g_tj[tt] = (unsigned char)(i + rem);
    }
}

__global__ void norm_kernel(const float* __restrict__ emb, const void* __restrict__ tgt) {
    int row = blockIdx.x;
    int t = threadIdx.x;
    float v = emb[row * Dd + t];
    float sq = v * v;
#pragma unroll
    for (int o = 16; o > 0; o >>= 1) sq += __shfl_down_sync(0xffffffffu, sq, o);
    __shared__ float sm[8];
    if ((t & 31) == 0) sm[t >> 5] = sq;
    __syncthreads();
    float tot = 0.f;
#pragma unroll
    for (int i = 0; i < 8; i++) tot += sm[i];
    float scale = 3.16227766016838f / fmaxf(sqrtf(tot), 1e-8f);  // sqrt(10)/max(||e||,eps)
    float e = v * scale;
    __nv_bfloat16 h = __float2bfloat16(e);
    float lo = e - __bfloat162float(h);
    g_E2[row * K2 + t] = h;                          // hi half: cols [0,256)
    g_E2[row * K2 + Dd + t] = __float2bfloat16(lo);  // lo half: cols [256,512)
    if (t == 0) {
        g_cls[row] = g_is64 ? (int)((const long long*)tgt)[row]
                            : ((const int*)tgt)[row];
    }
}

// ---------------- main fused symmetric HMMA kernel ----------------
// One K-chunk = 128 rows x 128 bf16 cols (32KB), swizzled for ldmatrix.
__device__ __forceinline__ void loadChunk(uint32_t sb, int stage, int blkA, int blkB,
                                          int kc, int tid) {
    uint32_t aBase = sb + SM_AOFF(stage);
    uint32_t bBase = sb + SM_BOFF(stage);
#pragma unroll
    for (int it = 0; it < 8; it++) {
        int idx = it * 256 + tid;
        int r = idx >> 4, c = idx & 15;
        uint32_t off = r * 256 + ((c ^ (r & 7)) << 4);
        CP16(aBase + off, (const char*)&g_E2[(blkA * 128 + r) * K2 + kc * 128] + c * 16);
        CP16(bBase + off, (const char*)&g_E2[(blkB * 128 + r) * K2 + kc * 128] + c * 16);
    }
    CP_COMMIT();
}

__global__ void __launch_bounds__(256, 1) main_kernel() {
    extern __shared__ char smem[];
    uint32_t sb = smem_u32(smem);
    int tid = threadIdx.x, lane = tid & 31, wid = tid >> 5;
    int wr = wid & 3, wc = wid >> 2;          // 4 row-warps x 2 col-warps
    int laneHi = lane >> 4;

    // fragment geometry (identical mapping to validated R3 kernel)
    uint32_t rowOffA[2]; int axor[2];
#pragma unroll
    for (int i = 0; i < 2; i++) {
        int r = wr * 32 + i * 16 + (lane & 15);
        rowOffA[i] = r * 256; axor[i] = r & 7;
    }
    uint32_t rowOffB[4]; int bxor[4];
#pragma unroll
    for (int g = 0; g < 4; g++) {
        int r = wc * 64 + g * 16 + (lane & 15);
        rowOffB[g] = r * 256; bxor[g] = r & 7;
    }
    int li[4];
#pragma unroll
    for (int s = 0; s < 4; s++) li[s] = wr * 32 + (s >> 1) * 16 + (s & 1) * 8 + (lane >> 2);
    int lcBase = wc * 64 + (lane & 3) * 2;    // local col base; col n adds n*8

    float* redRowN = (float*)(smem + SM_RED);            // 256
    float* redRowP = redRowN + 256;                      // 256
    float* redColN = redRowP + 256;                      // 512
    float* redColP = redColN + 512;                      // 512

    int t0 = blockIdx.x;
    if (t0 >= NTILES) return;
    int bi = g_ti[t0], bj = g_tj[t0];
    loadChunk(sb, 0, bi, bj, 0, tid);

    int stage = 0;
    for (int t = t0; t < NTILES; t += GRID_MAIN) {
        bool isDiag = (bi == bj);

        int clsR[4];
#pragma unroll
        for (int s = 0; s < 4; s++) clsR[s] = g_cls[bi * 128 + li[s]];
        int clsC0[8], clsC1[8];
#pragma unroll
        for (int n = 0; n < 8; n++) {
            clsC0[n] = g_cls[bj * 128 + lcBase + n * 8];
            clsC1[n] = g_cls[bj * 128 + lcBase + n * 8 + 1];
        }

        float cAcc[2][8][4];
#pragma unroll
        for (int i = 0; i < 2; i++)
#pragma unroll
            for (int n = 0; n < 8; n++)
#pragma unroll
                for (int v = 0; v < 4; v++) cAcc[i][n][v] = 0.f;

        for (int kc = 0; kc < 4; kc++) {
            // prefetch next chunk (crosses tile boundary)
            int nbi = bi, nbj = bj, nkc = kc + 1;
            bool more = true;
            if (nkc == 4) {
                int nt = t + GRID_MAIN;
                if (nt < NTILES) { nbi = g_ti[nt]; nbj = g_tj[nt]; nkc = 0; }
                else more = false;
            }
            if (more) { loadChunk(sb, stage ^ 1, nbi, nbj, nkc, tid); CP_WAIT1(); }
            else      { CP_WAIT0(); }
            __syncthreads();

            uint32_t aB = sb + SM_AOFF(stage), bB = sb + SM_BOFF(stage);
#pragma unroll
            for (int ks = 0; ks < 8; ks++) {
                uint32_t a[2][4], b[4][4];
                int ch = ks * 2 + laneHi;
#pragma unroll
                for (int i = 0; i < 2; i++) LDM4(a[i], aB + rowOffA[i] + ((ch ^ axor[i]) << 4));
#pragma unroll
                for (int g = 0; g < 4; g++) LDM4(b[g], bB + rowOffB[g] + ((ch ^ bxor[g]) << 4));
#pragma unroll
                for (int i = 0; i < 2; i++)
#pragma unroll
                    for (int n = 0; n < 8; n++)
                        MMA(cAcc[i][n], a[i], b[n >> 1][n & 1], b[n >> 1][(n & 1) + 2]);
            }
            stage ^= 1;
            __syncthreads();   // all warps done with this stage before it is overwritten
        }

        // ---- fused epilogue: exp + masks + row/col accumulation ----
        float negA[4] = {0.f, 0.f, 0.f, 0.f}, posA[4] = {0.f, 0.f, 0.f, 0.f};
        float colN[16], colP[16];
#pragma unroll
        for (int x = 0; x < 16; x++) { colN[x] = 0.f; colP[x] = 0.f; }

        if (isDiag) {
#pragma unroll
            for (int n = 0; n < 8; n++) {
                int c0 = lcBase + n * 8, c1 = c0 + 1;
#pragma unroll
                for (int i = 0; i < 2; i++) {
                    int s0 = 2 * i, s1 = 2 * i + 1;
                    float e00 = __expf(cAcc[i][n][0]);
                    float e01 = __expf(cAcc[i][n][1]);
                    float e10 = __expf(cAcc[i][n][2]);
                    float e11 = __expf(cAcc[i][n][3]);
                    if (clsC0[n] == clsR[s0]) { if (c0 != li[s0]) posA[s0] += e00; } else negA[s0] += e00;
                    if (clsC1[n] == clsR[s0]) { if (c1 != li[s0]) posA[s0] += e01; } else negA[s0] += e01;
                    if (clsC0[n] == clsR[s1]) { if (c0 != li[s1]) posA[s1] += e10; } else negA[s1] += e10;
                    if (clsC1[n] == clsR[s1]) { if (c1 != li[s1]) posA[s1] += e11; } else negA[s1] += e11;
                }
            }
        } else {
#pragma unroll
            for (int n = 0; n < 8; n++) {
#pragma unroll
                for (int i = 0; i < 2; i++) {
                    int s0 = 2 * i, s1 = 2 * i + 1;
                    float e00 = __expf(cAcc[i][n][0]);
                    float e01 = __expf(cAcc[i][n][1]);
                    float e10 = __expf(cAcc[i][n][2]);
                    float e11 = __expf(cAcc[i][n][3]);
                    if (clsC0[n] == clsR[s0]) { posA[s0] += e00; colP[2*n]   += e00; }
                    else                      { negA[s0] += e00; colN[2*n]   += e00; }
                    if (clsC1[n] == clsR[s0]) { posA[s0] += e01; colP[2*n+1] += e01; }
                    else                      { negA[s0] += e01; colN[2*n+1] += e01; }
                    if (clsC0[n] == clsR[s1]) { posA[s1] += e10; colP[2*n]   += e10; }
                    else                      { negA[s1] += e10; colN[2*n]   += e10; }
                    if (clsC1[n] == clsR[s1]) { posA[s1] += e11; colP[2*n+1] += e11; }
                    else                      { negA[s1] += e11; colN[2*n+1] += e11; }
                }
            }
        }

        // row reduce: lanes sharing a row differ in lane&3
#pragma unroll
        for (int s = 0; s < 4; s++) {
            negA[s] += __shfl_xor_sync(0xffffffffu, negA[s], 1);
            negA[s] += __shfl_xor_sync(0xffffffffu, negA[s], 2);
            posA[s] += __shfl_xor_sync(0xffffffffu, posA[s], 1);
            posA[s] += __shfl_xor_sync(0xffffffffu, posA[s], 2);
        }
        if ((lane & 3) == 0) {
#pragma unroll
            for (int s = 0; s < 4; s++) {
                redRowN[wc * 128 + li[s]] = negA[s];
                redRowP[wc * 128 + li[s]] = posA[s];
            }
        }
        // col reduce: lanes sharing a col differ in lane>>2
        if (!isDiag) {
#pragma unroll
            for (int x = 0; x < 16; x++) {
                colN[x] += __shfl_xor_sync(0xffffffffu, colN[x], 4);
                colN[x] += __shfl_xor_sync(0xffffffffu, colN[x], 8);
                colN[x] += __shfl_xor_sync(0xffffffffu, colN[x], 16);
                colP[x] += __shfl_xor_sync(0xffffffffu, colP[x], 4);
                colP[x] += __shfl_xor_sync(0xffffffffu, colP[x], 8);
                colP[x] += __shfl_xor_sync(0xffffffffu, colP[x], 16);
            }
            if (lane < 4) {
#pragma unroll
                for (int n = 0; n < 8; n++) {
                    int lc = wc * 64 + n * 8 + lane * 2;
                    redColN[wr * 128 + lc]     = colN[2 * n];
                    redColN[wr * 128 + lc + 1] = colN[2 * n + 1];
                    redColP[wr * 128 + lc]     = colP[2 * n];
                    redColP[wr * 128 + lc + 1] = colP[2 * n + 1];
                }
            }
        }
        __syncthreads();
        if (tid < 128) {
            float rn = redRowN[tid] + redRowN[128 + tid];
            float rp = redRowP[tid] + redRowP[128 + tid];
            g_negP[bj * Nn + bi * 128 + tid] = rn;
            g_posP[bj * Nn + bi * 128 + tid] = rp;
            if (!isDiag) {
                float cn = redColN[tid] + redColN[128 + tid] + redColN[256 + tid] + redColN[384 + tid];
                float cp = redColP[tid] + redColP[128 + tid] + redColP[256 + tid] + redColP[384 + tid];
                g_negP[bi * Nn + bj * 128 + tid] = cn;
                g_posP[bi * Nn + bj * 128 + tid] = cp;
            }
        }

        int nt2 = t + GRID_MAIN;
        if (nt2 < NTILES) { bi = g_ti[nt2]; bj = g_tj[nt2]; }
    }
}

// ---------------- finalize ----------------
__global__ void finalize1_kernel() {
    int r = blockIdx.x * 256 + threadIdx.x;
    float ng = 0.f, ps = 0.f;
#pragma unroll
    for (int s = 0; s < NBLK; s++) {
        ng += g_negP[s * Nn + r];
        ps += g_posP[s * Nn + r];
    }
    float local = logf(ng) - logf(ps);
    int t = threadIdx.x;
#pragma unroll
    for (int o = 16; o > 0; o >>= 1) local += __shfl_down_sync(0xffffffffu, local, o);
    __shared__ float sm[8];
    if ((t & 31) == 0) sm[t >> 5] = local;
    __syncthreads();
    if (t == 0) {
        float tot = 0.f;
#pragma unroll
        for (int i = 0; i < 8; i++) tot += sm[i];
        g_lossP[blockIdx.x] = tot;
    }
}

__global__ void finalize2_kernel(float* __restrict__ out) {
    int t = threadIdx.x;
    float v = (t < 32) ? g_lossP[t] : 0.f;
#pragma unroll
    for (int o = 16; o > 0; o >>= 1) v += __shfl_down_sync(0xffffffffu, v, o);
    if (t == 0) out[0] = v;
}

extern "C" void kernel_launch(void* const* d_in, const int* in_sizes, int n_in,
                              void* d_out, int out_size) {
    const float* emb = (const float*)d_in[0];
    const void* tgt = d_in[1];

    cudaFuncSetAttribute(main_kernel, cudaFuncAttributeMaxDynamicSharedMemorySize, SM_TOTAL);

    detect_kernel<<<1, 256>>>((const int*)tgt);
    norm_kernel<<<Nn, 256>>>(emb, tgt);
    main_kernel<<<GRID_MAIN, 256, SM_TOTAL>>>();
    finalize1_kernel<<<32, 256>>>();
    finalize2_kernel<<<1, 32>>>((float*)d_out);
}

// round 5
// speedup vs baseline: 9.7686x; 1.5200x over previous
#include <cuda_runtime.h>
#include <cuda_bf16.h>
#include <cstdint>

// Problem constants
#define Nn 8192
#define Dd 256
#define NBLK 64           // 8192 / 128
#define NTILES 2080       // upper triangle incl diagonal: 64*65/2
#define GRID_MAIN 152

// SMEM layout (bytes): 2-stage A (32KB) + 2-stage B (32KB) + reduction area
#define STAGE_SZ 32768
#define SM_AOFF(s) ((s) * STAGE_SZ)
#define SM_BOFF(s) (65536 + (s) * STAGE_SZ)
#define SM_RED 131072
#define SM_TOTAL (131072 + 6144)

// scale folds 1/T and log2(e):  sqrt(10 * log2(e))
#define SCALE_C 3.79828197f

// Scratch (__device__ globals: allocation-free rule)
__device__ __nv_bfloat16 g_Eh[Nn * Dd];
__device__ int   g_cls[Nn];
__device__ float g_totP[NBLK * Nn];
__device__ float g_posP[NBLK * Nn];
__device__ float g_lossP[64];
__device__ unsigned char g_ti[NTILES], g_tj[NTILES];

// ---------------- PTX helpers (family-safe) ----------------
__device__ __forceinline__ uint32_t smem_u32(const void* p) {
    uint32_t a;
    asm("{ .reg .u64 t; cvta.to.shared.u64 t, %1; cvt.u32.u64 %0, t; }" : "=r"(a) : "l"(p));
    return a;
}
#define CP16(dst, src) asm volatile("cp.async.cg.shared.global [%0], [%1], 16;" :: "r"(dst), "l"(src))
#define CP_COMMIT() asm volatile("cp.async.commit_group;" ::: "memory")
#define CP_WAIT0() asm volatile("cp.async.wait_group 0;" ::: "memory")
#define CP_WAIT1() asm volatile("cp.async.wait_group 1;" ::: "memory")

#define LDM4(r, a) \
    asm volatile("ldmatrix.sync.aligned.m8n8.x4.shared.b16 {%0,%1,%2,%3}, [%4];" \
        : "=r"((r)[0]), "=r"((r)[1]), "=r"((r)[2]), "=r"((r)[3]) : "r"(a))

#define MMA(c, a, b0, b1) \
    asm volatile("mma.sync.aligned.m16n8k16.row.col.f32.bf16.bf16.f32 " \
        "{%0,%1,%2,%3}, {%4,%5,%6,%7}, {%8,%9}, {%0,%1,%2,%3};" \
        : "+f"((c)[0]), "+f"((c)[1]), "+f"((c)[2]), "+f"((c)[3]) \
        : "r"((a)[0]), "r"((a)[1]), "r"((a)[2]), "r"((a)[3]), "r"(b0), "r"(b1))

__device__ __forceinline__ float ex2f(float x) {
    float r;
    asm("ex2.approx.f32 %0, %1;" : "=f"(r) : "f"(x));
    return r;
}
__device__ __forceinline__ unsigned long long pack2(float lo, float hi) {
    unsigned long long r;
    asm("mov.b64 %0, {%1,%2};" : "=l"(r) : "f"(lo), "f"(hi));
    return r;
}
__device__ __forceinline__ void unpack2(unsigned long long v, float& lo, float& hi) {
    asm("mov.b64 {%0,%1}, %2;" : "=f"(lo), "=f"(hi) : "l"(v));
}
#define ADD2(d, a) asm("add.rn.f32x2 %0, %0, %1;" : "+l"(d) : "l"(a))

// ---------------- setup: dtype detect + class extraction + tile map ----------------
__global__ void detcls_kernel(const void* __restrict__ tgt) {
    __shared__ int sflag;
    const int* t32 = (const int*)tgt;
    int tid = threadIdx.x;
    int acc = 0;
    for (int k = tid; k < Nn / 2; k += 256) acc |= t32[2 * k + 1];
    acc = __reduce_or_sync(0xffffffffu, acc);
    __shared__ int sor[8];
    if ((tid & 31) == 0) sor[tid >> 5] = acc;
    __syncthreads();
    if (tid == 0) {
        int v = 0;
#pragma unroll
        for (int i = 0; i < 8; i++) v |= sor[i];
        sflag = (v == 0) ? 1 : 0;
    }
    __syncthreads();
    int is64 = sflag;
    const long long* t64 = (const long long*)tgt;
    for (int r = tid; r < Nn; r += 256)
        g_cls[r] = is64 ? (int)t64[r] : t32[r];
    for (int tt = tid; tt < NTILES; tt += 256) {
        int i = 0, rem = tt;
        while (rem >= NBLK - i) { rem -= NBLK - i; i++; }
        g_ti[tt] = (unsigned char)i;
        g_tj[tt] = (unsigned char)(i + rem);
    }
}

// ---------------- normalize: warp per row, fold sqrt(10*log2e) ----------------
__global__ void norm_kernel(const float* __restrict__ emb) {
    int tid = threadIdx.x, lane = tid & 31, wid = tid >> 5;
    int row = blockIdx.x * 8 + wid;
    const float4* src = (const float4*)&emb[row * Dd + lane * 8];
    float4 v0 = src[0], v1 = src[1];
    float sq = v0.x * v0.x + v0.y * v0.y + v0.z * v0.z + v0.w * v0.w
             + v1.x * v1.x + v1.y * v1.y + v1.z * v1.z + v1.w * v1.w;
#pragma unroll
    for (int o = 16; o > 0; o >>= 1) sq += __shfl_xor_sync(0xffffffffu, sq, o);
    float scale = SCALE_C / fmaxf(sqrtf(sq), 1e-8f);
    __nv_bfloat162 h0 = __floats2bfloat162_rn(v0.x * scale, v0.y * scale);
    __nv_bfloat162 h1 = __floats2bfloat162_rn(v0.z * scale, v0.w * scale);
    __nv_bfloat162 h2 = __floats2bfloat162_rn(v1.x * scale, v1.y * scale);
    __nv_bfloat162 h3 = __floats2bfloat162_rn(v1.z * scale, v1.w * scale);
    uint4 out;
    out.x = *(uint32_t*)&h0; out.y = *(uint32_t*)&h1;
    out.z = *(uint32_t*)&h2; out.w = *(uint32_t*)&h3;
    *(uint4*)&g_Eh[row * Dd + lane * 8] = out;
}

// ---------------- main fused symmetric HMMA kernel (K=256, hi only) ----------------
// One K-chunk = 128 rows x 128 bf16 cols (32KB), swizzled for ldmatrix.
__device__ __forceinline__ void loadChunk(uint32_t sb, int stage, int blkA, int blkB,
                                          int kc, int tid) {
    uint32_t aBase = sb + SM_AOFF(stage);
    uint32_t bBase = sb + SM_BOFF(stage);
#pragma unroll
    for (int it = 0; it < 8; it++) {
        int idx = it * 256 + tid;
        int r = idx >> 4, c = idx & 15;
        uint32_t off = r * 256 + ((c ^ (r & 7)) << 4);
        CP16(aBase + off, (const char*)&g_Eh[(blkA * 128 + r) * Dd + kc * 128] + c * 16);
        CP16(bBase + off, (const char*)&g_Eh[(blkB * 128 + r) * Dd + kc * 128] + c * 16);
    }
    CP_COMMIT();
}

__global__ void __launch_bounds__(256, 1) main_kernel() {
    extern __shared__ char smem[];
    uint32_t sb = smem_u32(smem);
    int tid = threadIdx.x, lane = tid & 31, wid = tid >> 5;
    int wr = wid & 3, wc = wid >> 2;          // 4 row-warps x 2 col-warps
    int laneHi = lane >> 4;

    uint32_t rowOffA[2]; int axor[2];
#pragma unroll
    for (int i = 0; i < 2; i++) {
        int r = wr * 32 + i * 16 + (lane & 15);
        rowOffA[i] = r * 256; axor[i] = r & 7;
    }
    uint32_t rowOffB[4]; int bxor[4];
#pragma unroll
    for (int g = 0; g < 4; g++) {
        int r = wc * 64 + g * 16 + (lane & 15);
        rowOffB[g] = r * 256; bxor[g] = r & 7;
    }
    int li[4];
#pragma unroll
    for (int s = 0; s < 4; s++) li[s] = wr * 32 + (s >> 1) * 16 + (s & 1) * 8 + (lane >> 2);
    int lcBase = wc * 64 + (lane & 3) * 2;

    float* redRowT = (float*)(smem + SM_RED);            // 256
    float* redRowP = redRowT + 256;                      // 256
    float* redColT = redRowP + 256;                      // 512
    float* redColP = redColT + 512;                      // 512

    int t0 = blockIdx.x;
    if (t0 >= NTILES) return;
    int bi = g_ti[t0], bj = g_tj[t0];
    loadChunk(sb, 0, bi, bj, 0, tid);

    int stage = 0;
    for (int t = t0; t < NTILES; t += GRID_MAIN) {
        bool isDiag = (bi == bj);

        int clsR[4];
#pragma unroll
        for (int s = 0; s < 4; s++) clsR[s] = g_cls[bi * 128 + li[s]];
        int clsC0[8], clsC1[8];
#pragma unroll
        for (int n = 0; n < 8; n++) {
            clsC0[n] = g_cls[bj * 128 + lcBase + n * 8];
            clsC1[n] = g_cls[bj * 128 + lcBase + n * 8 + 1];
        }

        float cAcc[2][8][4];
#pragma unroll
        for (int i = 0; i < 2; i++)
#pragma unroll
            for (int n = 0; n < 8; n++)
#pragma unroll
                for (int v = 0; v < 4; v++) cAcc[i][n][v] = 0.f;

        for (int kc = 0; kc < 2; kc++) {
            int nbi = bi, nbj = bj, nkc = kc + 1;
            bool more = true;
            if (nkc == 2) {
                int nt = t + GRID_MAIN;
                if (nt < NTILES) { nbi = g_ti[nt]; nbj = g_tj[nt]; nkc = 0; }
                else more = false;
            }
            if (more) { loadChunk(sb, stage ^ 1, nbi, nbj, nkc, tid); CP_WAIT1(); }
            else      { CP_WAIT0(); }
            __syncthreads();

            uint32_t aB = sb + SM_AOFF(stage), bB = sb + SM_BOFF(stage);
#pragma unroll
            for (int ks = 0; ks < 8; ks++) {
                uint32_t a[2][4], b[4][4];
                int ch = ks * 2 + laneHi;
#pragma unroll
                for (int i = 0; i < 2; i++) LDM4(a[i], aB + rowOffA[i] + ((ch ^ axor[i]) << 4));
#pragma unroll
                for (int g = 0; g < 4; g++) LDM4(b[g], bB + rowOffB[g] + ((ch ^ bxor[g]) << 4));
#pragma unroll
                for (int i = 0; i < 2; i++)
#pragma unroll
                    for (int n = 0; n < 8; n++)
                        MMA(cAcc[i][n], a[i], b[n >> 1][n & 1], b[n >> 1][(n & 1) + 2]);
            }
            stage ^= 1;
            __syncthreads();
        }

        // ---- fused epilogue: ex2 + tot (packed) + pos (predicated) ----
        float rowTot[4] = {0.f, 0.f, 0.f, 0.f}, rowPos[4] = {0.f, 0.f, 0.f, 0.f};
        float colPos[16];
        unsigned long long colTot2[8];
#pragma unroll
        for (int x = 0; x < 16; x++) colPos[x] = 0.f;
#pragma unroll
        for (int n = 0; n < 8; n++) colTot2[n] = 0ull;

        if (isDiag) {
#pragma unroll
            for (int n = 0; n < 8; n++) {
                int c0 = lcBase + n * 8, c1 = c0 + 1;
#pragma unroll
                for (int i = 0; i < 2; i++) {
                    int s0 = 2 * i, s1 = 2 * i + 1;
                    float e0 = ex2f(cAcc[i][n][0]);
                    float e1 = ex2f(cAcc[i][n][1]);
                    float e2 = ex2f(cAcc[i][n][2]);
                    float e3 = ex2f(cAcc[i][n][3]);
                    if (c0 != li[s0]) { rowTot[s0] += e0; if (clsC0[n] == clsR[s0]) rowPos[s0] += e0; }
                    if (c1 != li[s0]) { rowTot[s0] += e1; if (clsC1[n] == clsR[s0]) rowPos[s0] += e1; }
                    if (c0 != li[s1]) { rowTot[s1] += e2; if (clsC0[n] == clsR[s1]) rowPos[s1] += e2; }
                    if (c1 != li[s1]) { rowTot[s1] += e3; if (clsC1[n] == clsR[s1]) rowPos[s1] += e3; }
                }
            }
        } else {
            unsigned long long rowTot2[2] = {0ull, 0ull};
#pragma unroll
            for (int n = 0; n < 8; n++) {
#pragma unroll
                for (int i = 0; i < 2; i++) {
                    int s0 = 2 * i, s1 = 2 * i + 1;
                    float e0 = ex2f(cAcc[i][n][0]);
                    float e1 = ex2f(cAcc[i][n][1]);
                    float e2 = ex2f(cAcc[i][n][2]);
                    float e3 = ex2f(cAcc[i][n][3]);
                    ADD2(rowTot2[i], pack2(e0, e2));
                    ADD2(rowTot2[i], pack2(e1, e3));
                    ADD2(colTot2[n], pack2(e0, e1));
                    ADD2(colTot2[n], pack2(e2, e3));
                    if (clsC0[n] == clsR[s0]) { rowPos[s0] += e0; colPos[2 * n] += e0; }
                    if (clsC1[n] == clsR[s0]) { rowPos[s0] += e1; colPos[2 * n + 1] += e1; }
                    if (clsC0[n] == clsR[s1]) { rowPos[s1] += e2; colPos[2 * n] += e2; }
                    if (clsC1[n] == clsR[s1]) { rowPos[s1] += e3; colPos[2 * n + 1] += e3; }
                }
            }
#pragma unroll
            for (int i = 0; i < 2; i++) {
                float a, b;
                unpack2(rowTot2[i], a, b);
                rowTot[2 * i] = a; rowTot[2 * i + 1] = b;
            }
        }

        // row reduce: lanes sharing a row differ in lane&3
#pragma unroll
        for (int s = 0; s < 4; s++) {
            rowTot[s] += __shfl_xor_sync(0xffffffffu, rowTot[s], 1);
            rowTot[s] += __shfl_xor_sync(0xffffffffu, rowTot[s], 2);
            rowPos[s] += __shfl_xor_sync(0xffffffffu, rowPos[s], 1);
            rowPos[s] += __shfl_xor_sync(0xffffffffu, rowPos[s], 2);
        }
        if ((lane & 3) == 0) {
#pragma unroll
            for (int s = 0; s < 4; s++) {
                redRowT[wc * 128 + li[s]] = rowTot[s];
                redRowP[wc * 128 + li[s]] = rowPos[s];
            }
        }
        if (!isDiag) {
            float colT[16];
#pragma unroll
            for (int n = 0; n < 8; n++) {
                float a, b;
                unpack2(colTot2[n], a, b);
                colT[2 * n] = a; colT[2 * n + 1] = b;
            }
#pragma unroll
            for (int x = 0; x < 16; x++) {
                colT[x] += __shfl_xor_sync(0xffffffffu, colT[x], 4);
                colT[x] += __shfl_xor_sync(0xffffffffu, colT[x], 8);
                colT[x] += __shfl_xor_sync(0xffffffffu, colT[x], 16);
                colPos[x] += __shfl_xor_sync(0xffffffffu, colPos[x], 4);
                colPos[x] += __shfl_xor_sync(0xffffffffu, colPos[x], 8);
                colPos[x] += __shfl_xor_sync(0xffffffffu, colPos[x], 16);
            }
            if (lane < 4) {
#pragma unroll
                for (int n = 0; n < 8; n++) {
                    int lc = wc * 64 + n * 8 + lane * 2;
                    redColT[wr * 128 + lc]     = colT[2 * n];
                    redColT[wr * 128 + lc + 1] = colT[2 * n + 1];
                    redColP[wr * 128 + lc]     = colPos[2 * n];
                    redColP[wr * 128 + lc + 1] = colPos[2 * n + 1];
                }
            }
        }
        __syncthreads();
        if (tid < 128) {
            float rt = redRowT[tid] + redRowT[128 + tid];
            float rp = redRowP[tid] + redRowP[128 + tid];
            g_totP[bj * Nn + bi * 128 + tid] = rt;
            g_posP[bj * Nn + bi * 128 + tid] = rp;
            if (!isDiag) {
                float ct = redColT[tid] + redColT[128 + tid] + redColT[256 + tid] + redColT[384 + tid];
                float cp = redColP[tid] + redColP[128 + tid] + redColP[256 + tid] + redColP[384 + tid];
                g_totP[bi * Nn + bj * 128 + tid] = ct;
                g_posP[bi * Nn + bj * 128 + tid] = cp;
            }
        }

        int nt2 = t + GRID_MAIN;
        if (nt2 < NTILES) { bi = g_ti[nt2]; bj = g_tj[nt2]; }
    }
}

// ---------------- finalize ----------------
__global__ void finalize1_kernel() {
    int r = blockIdx.x * 128 + threadIdx.x;
    float tt = 0.f, pp = 0.f;
#pragma unroll
    for (int s = 0; s < NBLK; s++) {
        tt += g_totP[s * Nn + r];
        pp += g_posP[s * Nn + r];
    }
    float local = logf(tt - pp) - logf(pp);
    int t = threadIdx.x;
#pragma unroll
    for (int o = 16; o > 0; o >>= 1) local += __shfl_down_sync(0xffffffffu, local, o);
    __shared__ float sm[4];
    if ((t & 31) == 0) sm[t >> 5] = local;
    __syncthreads();
    if (t == 0) g_lossP[blockIdx.x] = sm[0] + sm[1] + sm[2] + sm[3];
}

__global__ void finalize2_kernel(float* __restrict__ out) {
    int t = threadIdx.x;
    float v = g_lossP[t] + g_lossP[t + 32];
#pragma unroll
    for (int o = 16; o > 0; o >>= 1) v += __shfl_down_sync(0xffffffffu, v, o);
    if (t == 0) out[0] = v;
}

extern "C" void kernel_launch(void* const* d_in, const int* in_sizes, int n_in,
                              void* d_out, int out_size) {
    const float* emb = (const float*)d_in[0];
    const void* tgt = d_in[1];

    cudaFuncSetAttribute(main_kernel, cudaFuncAttributeMaxDynamicSharedMemorySize, SM_TOTAL);

    detcls_kernel<<<1, 256>>>(tgt);
    norm_kernel<<<Nn / 8, 256>>>(emb);
    main_kernel<<<GRID_MAIN, 256, SM_TOTAL>>>();
    finalize1_kernel<<<64, 128>>>();
    finalize2_kernel<<<1, 32>>>((float*)d_out);
}